// round 1
// baseline (speedup 1.0000x reference)
#include <cuda_runtime.h>
#include <cuda_bf16.h>
#include <cstdint>

#define BB 4
#define CC 19
#define HH 512
#define WW 1024
#define HW (HH * WW)            // 524288 = 2^19
#define NPIX (BB * HW)          // 2097152
#define NBC (BB * CC)           // 76
#define EQCAP 2048
#define NTHREAD_MAIN 524288     // NPIX/4
#define NBLK_MAIN 2048          // NTHREAD_MAIN / 256

// ---------------- device scratch (static, zero-initialized at load) --------
__device__ unsigned int  g_u[NPIX];            // float bits of max_prob
__device__ float         g_nll[NPIX];          // nll = log(sum exp(x - max))
__device__ unsigned char g_cls[NPIX];          // argmax class
__device__ unsigned int  g_hist1[NBC * 1024];  // round-1 hist (u>>16 - 0x3D00)
__device__ unsigned int  g_hist2[NBC * 256];   // round-2/3 hist (reused)
__device__ unsigned int  g_prefix[NBC];
__device__ unsigned int  g_r[NBC];
__device__ unsigned int  g_tbits[NBC];         // exact k-th largest bits; 0xFFFFFFFF = no topk
__device__ unsigned int  g_m[NBC];             // # of equal-valued pixels to keep
__device__ unsigned int  g_eqn[NBC];
__device__ uint2         g_eq[NBC * EQCAP];    // (pixel index in image, nll bits)
__device__ float         g_blocksum[NBLK_MAIN];
__device__ float         g_eqsum[NBC];

// ---------------- main compute: online softmax + round-1 histogram ---------
#define UPD(V, MX, S, AM, C)                                                   \
    if ((V) > (MX)) { (S) = (S) * __expf((MX) - (V)) + 1.0f; (MX) = (V); (AM) = (C); } \
    else            { (S) += __expf((V) - (MX)); }

__global__ void __launch_bounds__(256) k_compute(const float* __restrict__ pred) {
    unsigned int t  = blockIdx.x * 256 + threadIdx.x;
    unsigned int p0 = t << 2;
    unsigned int b  = p0 >> 19;
    unsigned int n  = p0 & (HW - 1);

    // clear per-launch accumulators (graph replay safety)
    if (blockIdx.x == 0 && threadIdx.x < NBC) g_eqn[threadIdx.x] = 0;

    const float4* base = reinterpret_cast<const float4*>(pred + (size_t)b * CC * HW + n);
    const unsigned int cs = HW / 4;

    float4 x = __ldg(base);
    float m0 = x.x, m1 = x.y, m2 = x.z, m3 = x.w;
    float s0 = 1.f, s1 = 1.f, s2 = 1.f, s3 = 1.f;
    int   a0 = 0, a1 = 0, a2 = 0, a3 = 0;

#pragma unroll
    for (int c = 1; c < CC; c++) {
        float4 v = __ldg(base + (size_t)c * cs);
        UPD(v.x, m0, s0, a0, c);
        UPD(v.y, m1, s1, a1, c);
        UPD(v.z, m2, s2, a2, c);
        UPD(v.w, m3, s3, a3, c);
    }

    float nl0 = __logf(s0), nl1 = __logf(s1), nl2 = __logf(s2), nl3 = __logf(s3);
    float pr0 = 1.0f / s0,  pr1 = 1.0f / s1,  pr2 = 1.0f / s2,  pr3 = 1.0f / s3;
    unsigned int u0 = __float_as_uint(pr0), u1 = __float_as_uint(pr1);
    unsigned int u2 = __float_as_uint(pr2), u3 = __float_as_uint(pr3);

    *reinterpret_cast<uint4*>(g_u + p0)    = make_uint4(u0, u1, u2, u3);
    *reinterpret_cast<float4*>(g_nll + p0) = make_float4(nl0, nl1, nl2, nl3);
    *reinterpret_cast<uchar4*>(g_cls + p0) =
        make_uchar4((unsigned char)a0, (unsigned char)a1, (unsigned char)a2, (unsigned char)a3);

#define H1(U, A) {                                                             \
        int bin = (int)((U) >> 16) - 0x3D00;                                   \
        bin = bin < 0 ? 0 : (bin > 1023 ? 1023 : bin);                         \
        atomicAdd(&g_hist1[(b * CC + (unsigned)(A)) * 1024 + (unsigned)bin], 1u); }
    H1(u0, a0); H1(u1, a1); H1(u2, a2); H1(u3, a3);
#undef H1
}

// ---------------- round-1 select: count, k = floor(0.66*count), find prefix
__global__ void __launch_bounds__(256) k_sel1() {
    int bc = blockIdx.x;
    unsigned int* h = g_hist1 + (size_t)bc * 1024;
    __shared__ unsigned int sh[1024];
    __shared__ unsigned int csum[256];
    __shared__ unsigned int red[256];
    int t = threadIdx.x;

    unsigned int ps = 0;
#pragma unroll
    for (int i = 0; i < 4; i++) { unsigned int v = h[4 * t + i]; sh[4 * t + i] = v; ps += v; }
    csum[t] = ps;
    red[t]  = ps;
    __syncthreads();
    for (int s = 128; s > 0; s >>= 1) { if (t < s) red[t] += red[t + s]; __syncthreads(); }

    if (t == 0) {
        unsigned int count = red[0];
        unsigned int k = (unsigned int)floorf((float)count * 0.66f);
        if (k == 0) {
            g_tbits[bc] = 0xFFFFFFFFu; g_m[bc] = 0;
            g_prefix[bc] = 0xFFFFFFFFu; g_r[bc] = 0;
        } else {
            unsigned int cum = 0;
            int ch = 255;
            for (;;) {
                unsigned int cv = csum[ch];
                if (cum + cv >= k || ch == 0) break;
                cum += cv; ch--;
            }
            int bin = ch * 4 + 3;
            for (;;) {
                unsigned int hb = sh[bin];
                if (cum + hb >= k || bin == ch * 4) break;
                cum += hb; bin--;
            }
            g_prefix[bc] = (unsigned int)bin + 0x3D00u;   // == (u >> 16) of threshold
            g_r[bc]      = k - cum;                       // remaining rank within bin
            g_tbits[bc]  = 0u;                            // "active" marker
        }
    }
    __syncthreads();
#pragma unroll
    for (int i = 0; i < 4; i++) h[4 * t + i] = 0;         // leave clean for next replay
}

// ---------------- rounds 2/3: refine 8 bits. shift=8 then shift=0 ----------
__global__ void __launch_bounds__(256) k_hist(int shift) {
    unsigned int t  = blockIdx.x * 256 + threadIdx.x;
    unsigned int p0 = t << 2;
    unsigned int b  = p0 >> 19;
    uint4  u  = *reinterpret_cast<const uint4*>(g_u + p0);
    uchar4 cl = *reinterpret_cast<const uchar4*>(g_cls + p0);
#define H2(U, C) {                                                             \
        unsigned int bc = b * CC + (unsigned)(C);                              \
        if (((U) >> (shift + 8)) == g_prefix[bc])                              \
            atomicAdd(&g_hist2[bc * 256 + (((U) >> shift) & 255u)], 1u); }
    H2(u.x, cl.x); H2(u.y, cl.y); H2(u.z, cl.z); H2(u.w, cl.w);
#undef H2
}

__global__ void __launch_bounds__(256) k_sel23(int is_final) {
    int bc = blockIdx.x;
    if (g_tbits[bc] == 0xFFFFFFFFu) return;               // row untouched, stays clean
    unsigned int* h = g_hist2 + bc * 256;
    __shared__ unsigned int sh[256];
    int t = threadIdx.x;
    sh[t] = h[t];
    __syncthreads();
    if (t == 0) {
        unsigned int r = g_r[bc];
        unsigned int cum = 0;
        int bin = 255;
        for (;;) {
            unsigned int hb = sh[bin];
            if (cum + hb >= r || bin == 0) break;
            cum += hb; bin--;
        }
        unsigned int npfx = (g_prefix[bc] << 8) | (unsigned int)bin;
        if (is_final) { g_tbits[bc] = npfx; g_m[bc] = r - cum; }
        else          { g_prefix[bc] = npfx; g_r[bc] = r - cum; }
    }
    __syncthreads();
    h[t] = 0;
}

// ---------------- final mask + NLL sum (deterministic per-block sums) ------
__global__ void __launch_bounds__(256) k_final() {
    unsigned int t  = blockIdx.x * 256 + threadIdx.x;
    unsigned int p0 = t << 2;
    unsigned int b  = p0 >> 19;
    unsigned int n  = p0 & (HW - 1);
    uint4  u  = *reinterpret_cast<const uint4*>(g_u + p0);
    float4 nl = *reinterpret_cast<const float4*>(g_nll + p0);
    uchar4 cl = *reinterpret_cast<const uchar4*>(g_cls + p0);

    float local = 0.f;
#define LANE(U, NL, C, J) {                                                    \
        unsigned int bc = b * CC + (unsigned)(C);                              \
        unsigned int tb = g_tbits[bc];                                         \
        if (__uint_as_float(U) > 0.9f || (U) > tb) local += (NL);              \
        else if ((U) == tb) {                                                  \
            unsigned int pos = atomicAdd(&g_eqn[bc], 1u);                      \
            if (pos < EQCAP)                                                   \
                g_eq[bc * EQCAP + pos] = make_uint2(n + (J), __float_as_uint(NL)); \
        } }
    LANE(u.x, nl.x, cl.x, 0);
    LANE(u.y, nl.y, cl.y, 1);
    LANE(u.z, nl.z, cl.z, 2);
    LANE(u.w, nl.w, cl.w, 3);
#undef LANE

    __shared__ float red[256];
    red[threadIdx.x] = local;
    __syncthreads();
    for (int s = 128; s > 0; s >>= 1) {
        if (threadIdx.x < s) red[threadIdx.x] += red[threadIdx.x + s];
        __syncthreads();
    }
    if (threadIdx.x == 0) g_blocksum[blockIdx.x] = red[0];
}

// ---------------- tie-break: keep first m equal-valued pixels by index -----
__global__ void __launch_bounds__(128) k_equal() {
    int bc = blockIdx.x;
    int t  = threadIdx.x;
    __shared__ float red[128];

    unsigned int tb = g_tbits[bc];
    unsigned int m  = g_m[bc];
    unsigned int E  = g_eqn[bc]; if (E > EQCAP) E = EQCAP;

    float local = 0.f;
    if (tb != 0xFFFFFFFFu && m > 0 && E > 0) {
        for (unsigned int i = t; i < E; i += 128) {
            uint2 e = g_eq[bc * EQCAP + i];
            unsigned int rank = 0;
            for (unsigned int j = 0; j < E; j++)
                rank += (g_eq[bc * EQCAP + j].x < e.x) ? 1u : 0u;
            if (rank < m) local += __uint_as_float(e.y);
        }
    }
    red[t] = local;
    __syncthreads();
    for (int s = 64; s > 0; s >>= 1) { if (t < s) red[t] += red[t + s]; __syncthreads(); }
    if (t == 0) g_eqsum[bc] = red[0];
}

// ---------------- final deterministic reduction to scalar ------------------
__global__ void __launch_bounds__(256) k_out(float* __restrict__ out) {
    __shared__ double red[256];
    int t = threadIdx.x;
    double acc = 0.0;
    for (int i = t; i < NBLK_MAIN; i += 256) acc += (double)g_blocksum[i];
    if (t < NBC) acc += (double)g_eqsum[t];
    red[t] = acc;
    __syncthreads();
    for (int s = 128; s > 0; s >>= 1) { if (t < s) red[t] += red[t + s]; __syncthreads(); }
    if (t == 0) out[0] = (float)(red[0] * (1.0 / (double)NPIX));
}

// ---------------- launcher --------------------------------------------------
extern "C" void kernel_launch(void* const* d_in, const int* in_sizes, int n_in,
                              void* d_out, int out_size) {
    const float* pred = (const float*)d_in[0];
    float* out = (float*)d_out;
    (void)in_sizes; (void)n_in; (void)out_size;

    k_compute<<<NBLK_MAIN, 256>>>(pred);
    k_sel1<<<NBC, 256>>>();
    k_hist<<<NBLK_MAIN, 256>>>(8);
    k_sel23<<<NBC, 256>>>(0);
    k_hist<<<NBLK_MAIN, 256>>>(0);
    k_sel23<<<NBC, 256>>>(1);
    k_final<<<NBLK_MAIN, 256>>>();
    k_equal<<<NBC, 128>>>();
    k_out<<<1, 256>>>(out);
}

// round 2
// speedup vs baseline: 1.5899x; 1.5899x over previous
#include <cuda_runtime.h>
#include <cuda_bf16.h>
#include <cstdint>

#define BB 4
#define CC 19
#define HH 512
#define WW 1024
#define HW (HH * WW)            // 524288 = 2^19
#define NPIX (BB * HW)          // 2097152
#define NBC (BB * CC)           // 76
#define EQCAP 2048
#define NBLK_MAIN 2048          // (NPIX/4) / 256

#define BINS1 160
#define BASE1 0xF50u            // bias for (u >> 18); u in [0x3D578D50, 0x3F800000]
#define BINS2 512

// ---------------- device scratch (static) -----------------------------------
__device__ unsigned int  g_u[NPIX];            // float bits of max_prob
__device__ float         g_nll[NPIX];          // nll = log(sum exp(x - max))
__device__ unsigned char g_cls[NPIX];          // argmax class
__device__ unsigned int  g_hist1[NBC * BINS1];
__device__ unsigned int  g_hist2[NBC * BINS2];
__device__ unsigned int  g_prefix[NBC];        // running high-bit prefix; 0xFFFFFFFF = inactive
__device__ unsigned int  g_r[NBC];             // remaining rank (1-indexed)
__device__ unsigned int  g_tbits[NBC];         // exact k-th largest bits; 0xFFFFFFFF = no topk
__device__ unsigned int  g_m[NBC];             // # of tie pixels (== tbits) to keep
__device__ unsigned int  g_eqn[NBC];
__device__ uint2         g_eq[NBC * EQCAP];    // (pixel index in image, nll bits)
__device__ float         g_blocksum[NBLK_MAIN];
__device__ float         g_eqsum[NBC];

// ---------------- main compute: online softmax + shared round-1 hist --------
#define UPD(V, MX, S, AM, C)                                                   \
    if ((V) > (MX)) { (S) = (S) * __expf((MX) - (V)) + 1.0f; (MX) = (V); (AM) = (C); } \
    else            { (S) += __expf((V) - (MX)); }

__global__ void __launch_bounds__(256) k_compute(const float* __restrict__ pred) {
    __shared__ unsigned int shist[CC * BINS1];           // 3040 u32 = 12.16 KB
    unsigned int tx = threadIdx.x;
    unsigned int t  = blockIdx.x * 256 + tx;
    unsigned int p0 = t << 2;
    unsigned int b  = blockIdx.x >> 9;                   // 512 blocks per image
    unsigned int n  = p0 & (HW - 1);

#pragma unroll
    for (int i = tx; i < CC * BINS1; i += 256) shist[i] = 0;
    if (blockIdx.x == 0 && tx < NBC) g_eqn[tx] = 0;      // graph-replay reset
    __syncthreads();

    const float4* base = reinterpret_cast<const float4*>(pred + (size_t)b * CC * HW + n);
    const unsigned int cs = HW / 4;

    float4 x = __ldg(base);
    float m0 = x.x, m1 = x.y, m2 = x.z, m3 = x.w;
    float s0 = 1.f, s1 = 1.f, s2 = 1.f, s3 = 1.f;
    int   a0 = 0, a1 = 0, a2 = 0, a3 = 0;

#pragma unroll
    for (int c = 1; c < CC; c++) {
        float4 v = __ldg(base + (size_t)c * cs);
        UPD(v.x, m0, s0, a0, c);
        UPD(v.y, m1, s1, a1, c);
        UPD(v.z, m2, s2, a2, c);
        UPD(v.w, m3, s3, a3, c);
    }

    float nl0 = __logf(s0), nl1 = __logf(s1), nl2 = __logf(s2), nl3 = __logf(s3);
    unsigned int u0 = __float_as_uint(1.0f / s0), u1 = __float_as_uint(1.0f / s1);
    unsigned int u2 = __float_as_uint(1.0f / s2), u3 = __float_as_uint(1.0f / s3);

    *reinterpret_cast<uint4*>(g_u + p0)    = make_uint4(u0, u1, u2, u3);
    *reinterpret_cast<float4*>(g_nll + p0) = make_float4(nl0, nl1, nl2, nl3);
    *reinterpret_cast<uchar4*>(g_cls + p0) =
        make_uchar4((unsigned char)a0, (unsigned char)a1, (unsigned char)a2, (unsigned char)a3);

#define H1(U, A) {                                                             \
        int bin = (int)((U) >> 18) - (int)BASE1;                               \
        bin = bin < 0 ? 0 : (bin > BINS1 - 1 ? BINS1 - 1 : bin);               \
        atomicAdd(&shist[(unsigned)(A) * BINS1 + (unsigned)bin], 1u); }
    H1(u0, a0); H1(u1, a1); H1(u2, a2); H1(u3, a3);
#undef H1
    __syncthreads();

#pragma unroll
    for (int i = tx; i < CC * BINS1; i += 256) {
        unsigned int v = shist[i];
        if (v) atomicAdd(&g_hist1[b * (CC * BINS1) + i], v);
    }
}

// ---------------- round-1 select: parallel suffix scan over 160 bins --------
__global__ void __launch_bounds__(256) k_sel1() {
    int bc = blockIdx.x;
    unsigned int* h = g_hist1 + bc * BINS1;
    __shared__ unsigned int suf[256];
    int t = threadIdx.x;

    unsigned int v = (t < BINS1) ? h[t] : 0;
    suf[t] = v;
    __syncthreads();
#pragma unroll
    for (int d = 1; d < 256; d <<= 1) {
        unsigned int x = suf[t];
        if (t + d < 256) x += suf[t + d];
        __syncthreads();
        suf[t] = x;
        __syncthreads();
    }

    unsigned int count = suf[0];
    unsigned int k = (unsigned int)floorf((float)count * 0.66f);

    if (k == 0) {
        if (t == 0) {
            g_tbits[bc] = 0xFFFFFFFFu; g_m[bc] = 0;
            g_prefix[bc] = 0xFFFFFFFFu; g_r[bc] = 0;
        }
    } else if (t < BINS1) {
        unsigned int above = suf[t + 1];                 // suf[160] == 0 (padded)
        if (suf[t] >= k && above < k) {
            g_prefix[bc] = (unsigned int)t + BASE1;      // == (u >> 18) of threshold
            g_r[bc]      = k - above;                    // 1-indexed rank within bin
            g_tbits[bc]  = 0u;                           // active marker
        }
    }
    __syncthreads();
    if (t < BINS1) h[t] = 0;                             // clean for next replay
}

// ---------------- rounds 2/3: refine 9 bits each (shift=9 then 0) -----------
__global__ void __launch_bounds__(256) k_hist(int shift) {
    __shared__ unsigned int spfx[CC];
    unsigned int tx = threadIdx.x;
    unsigned int t  = blockIdx.x * 256 + tx;
    unsigned int p0 = t << 2;
    unsigned int b  = blockIdx.x >> 9;
    if (tx < CC) spfx[tx] = g_prefix[b * CC + tx];
    __syncthreads();

    uint4  u  = *reinterpret_cast<const uint4*>(g_u + p0);
    uchar4 cl = *reinterpret_cast<const uchar4*>(g_cls + p0);
#define H2(U, C) {                                                             \
        if (((U) >> (shift + 9)) == spfx[(C)])                                 \
            atomicAdd(&g_hist2[(b * CC + (unsigned)(C)) * BINS2 +              \
                               (((U) >> shift) & (BINS2 - 1))], 1u); }
    H2(u.x, cl.x); H2(u.y, cl.y); H2(u.z, cl.z); H2(u.w, cl.w);
#undef H2
}

__global__ void __launch_bounds__(512) k_sel23(int is_final) {
    int bc = blockIdx.x;
    if (g_prefix[bc] == 0xFFFFFFFFu) return;             // row never dirtied
    unsigned int* h = g_hist2 + bc * BINS2;
    __shared__ unsigned int suf[BINS2];
    int t = threadIdx.x;

    suf[t] = h[t];
    __syncthreads();
#pragma unroll
    for (int d = 1; d < BINS2; d <<= 1) {
        unsigned int x = suf[t];
        if (t + d < BINS2) x += suf[t + d];
        __syncthreads();
        suf[t] = x;
        __syncthreads();
    }

    unsigned int r = g_r[bc];
    unsigned int above = (t == BINS2 - 1) ? 0u : suf[t + 1];
    if (suf[t] >= r && above < r) {
        unsigned int npfx = (g_prefix[bc] << 9) | (unsigned int)t;
        if (is_final) { g_tbits[bc] = npfx; g_m[bc] = r - above; }
        else          { g_prefix[bc] = npfx; g_r[bc] = r - above; }
    }
    __syncthreads();
    h[t] = 0;
}

// ---------------- final mask + NLL sum (deterministic per-block sums) -------
__global__ void __launch_bounds__(256) k_final() {
    __shared__ unsigned int stb[CC];
    __shared__ float red[256];
    unsigned int tx = threadIdx.x;
    unsigned int t  = blockIdx.x * 256 + tx;
    unsigned int p0 = t << 2;
    unsigned int b  = blockIdx.x >> 9;
    unsigned int n  = p0 & (HW - 1);
    if (tx < CC) stb[tx] = g_tbits[b * CC + tx];
    __syncthreads();

    uint4  u  = *reinterpret_cast<const uint4*>(g_u + p0);
    float4 nl = *reinterpret_cast<const float4*>(g_nll + p0);
    uchar4 cl = *reinterpret_cast<const uchar4*>(g_cls + p0);

    float local = 0.f;
#define LANE(U, NL, C, J) {                                                    \
        unsigned int tb = stb[(C)];                                            \
        if (__uint_as_float(U) > 0.9f || (U) > tb) local += (NL);              \
        else if ((U) == tb) {                                                  \
            unsigned int bc = b * CC + (unsigned)(C);                          \
            unsigned int pos = atomicAdd(&g_eqn[bc], 1u);                      \
            if (pos < EQCAP)                                                   \
                g_eq[bc * EQCAP + pos] = make_uint2(n + (J), __float_as_uint(NL)); \
        } }
    LANE(u.x, nl.x, cl.x, 0);
    LANE(u.y, nl.y, cl.y, 1);
    LANE(u.z, nl.z, cl.z, 2);
    LANE(u.w, nl.w, cl.w, 3);
#undef LANE

    red[tx] = local;
    __syncthreads();
    for (int s = 128; s > 0; s >>= 1) {
        if (tx < s) red[tx] += red[tx + s];
        __syncthreads();
    }
    if (tx == 0) g_blocksum[blockIdx.x] = red[0];
}

// ---------------- tie-break: keep first m equal-valued pixels by index ------
__global__ void __launch_bounds__(128) k_equal() {
    int bc = blockIdx.x;
    int t  = threadIdx.x;
    __shared__ float red[128];

    unsigned int tb = g_tbits[bc];
    unsigned int m  = g_m[bc];
    unsigned int E  = g_eqn[bc]; if (E > EQCAP) E = EQCAP;

    float local = 0.f;
    if (tb != 0xFFFFFFFFu && m > 0 && E > 0) {
        for (unsigned int i = t; i < E; i += 128) {
            uint2 e = g_eq[bc * EQCAP + i];
            unsigned int rank = 0;
            for (unsigned int j = 0; j < E; j++)
                rank += (g_eq[bc * EQCAP + j].x < e.x) ? 1u : 0u;
            if (rank < m) local += __uint_as_float(e.y);
        }
    }
    red[t] = local;
    __syncthreads();
    for (int s = 64; s > 0; s >>= 1) { if (t < s) red[t] += red[t + s]; __syncthreads(); }
    if (t == 0) g_eqsum[bc] = red[0];
}

// ---------------- final deterministic reduction to scalar -------------------
__global__ void __launch_bounds__(256) k_out(float* __restrict__ out) {
    __shared__ double red[256];
    int t = threadIdx.x;
    double acc = 0.0;
    for (int i = t; i < NBLK_MAIN; i += 256) acc += (double)g_blocksum[i];
    if (t < NBC) acc += (double)g_eqsum[t];
    red[t] = acc;
    __syncthreads();
    for (int s = 128; s > 0; s >>= 1) { if (t < s) red[t] += red[t + s]; __syncthreads(); }
    if (t == 0) out[0] = (float)(red[0] * (1.0 / (double)NPIX));
}

// ---------------- launcher ---------------------------------------------------
extern "C" void kernel_launch(void* const* d_in, const int* in_sizes, int n_in,
                              void* d_out, int out_size) {
    const float* pred = (const float*)d_in[0];
    float* out = (float*)d_out;
    (void)in_sizes; (void)n_in; (void)out_size;

    k_compute<<<NBLK_MAIN, 256>>>(pred);
    k_sel1<<<NBC, 256>>>();
    k_hist<<<NBLK_MAIN, 256>>>(9);
    k_sel23<<<NBC, BINS2>>>(0);
    k_hist<<<NBLK_MAIN, 256>>>(0);
    k_sel23<<<NBC, BINS2>>>(1);
    k_final<<<NBLK_MAIN, 256>>>();
    k_equal<<<NBC, 128>>>();
    k_out<<<1, 256>>>(out);
}